// round 7
// baseline (speedup 1.0000x reference)
#include <cuda_runtime.h>
#include <math.h>
#include <stdint.h>

#define BB   4
#define SS   2048
#define DD   1024
#define HH   16
#define DKK  64
#define DOUTT 1024
#define MM   (BB*SS)
#define N3   (3*HH*DKK)

// -------- scratch --------
__device__ float g_Wqkv[DD * N3];
__device__ float g_bqkv[N3];
__device__ float g_Wo[DD * DOUTT];
__device__ float g_xr[(size_t)MM * DD];
__device__ float g_QKV[(size_t)MM * N3];
__device__ float g_cat[(size_t)MM * DOUTT];

__device__ __forceinline__ unsigned f2tf32(float x) {
    unsigned r;
    asm("cvt.rna.tf32.f32 %0, %1;" : "=r"(r) : "f"(x));
    return r;
}

__device__ __forceinline__ void mma_tf32(float& c0, float& c1, float& c2, float& c3,
                                         unsigned a0, unsigned a1, unsigned a2, unsigned a3,
                                         unsigned b0, unsigned b1) {
    asm volatile(
        "mma.sync.aligned.m16n8k8.row.col.f32.tf32.tf32.f32 "
        "{%0,%1,%2,%3}, {%4,%5,%6,%7}, {%8,%9}, {%0,%1,%2,%3};\n"
        : "+f"(c0), "+f"(c1), "+f"(c2), "+f"(c3)
        : "r"(a0), "r"(a1), "r"(a2), "r"(a3), "r"(b0), "r"(b1));
}

__device__ __forceinline__ void cp16(unsigned* smem_ptr, const float* gmem_ptr) {
    unsigned dst = (unsigned)__cvta_generic_to_shared(smem_ptr);
    asm volatile("cp.async.cg.shared.global [%0], [%1], 16;\n" :: "r"(dst), "l"(gmem_ptr));
}
#define CP_COMMIT() asm volatile("cp.async.commit_group;\n" ::: "memory")
#define CP_WAIT(n)  asm volatile("cp.async.wait_group %0;\n" :: "n"(n) : "memory")

// within-8 pair permutation: feature j goes to position (j&3)*2 + (j>>2)
__host__ __device__ __forceinline__ int perm8(int j) {
    return ((j & 3) << 1) | (j >> 2);
}

// ============================================================
// Kernel 0: round x to tf32 grid
// ============================================================
__global__ void round_x_kernel(const float* __restrict__ x) {
    size_t i = (size_t)(blockIdx.x * blockDim.x + threadIdx.x) * 4;
    if (i < (size_t)MM * DD) {
        float4 v = *(const float4*)(x + i);
        float4 o;
        o.x = __uint_as_float(f2tf32(v.x));
        o.y = __uint_as_float(f2tf32(v.y));
        o.z = __uint_as_float(f2tf32(v.z));
        o.w = __uint_as_float(f2tf32(v.w));
        *(float4*)(g_xr + i) = o;
    }
}

// ============================================================
// Kernel 1: pack+round weights. Q,K head-dk columns are stored
// PAIR-PERMUTED (per 8-block) so attention can LDS.64 fragments.
// V and Wo natural.
// ============================================================
__global__ void pack_weights_kernel(const float* __restrict__ Wq,
                                    const float* __restrict__ bq,
                                    const float* __restrict__ Wk,
                                    const float* __restrict__ bk,
                                    const float* __restrict__ Wv,
                                    const float* __restrict__ bv,
                                    const float* __restrict__ Wo) {
    int idx = blockIdx.x * blockDim.x + threadIdx.x;
    const int per = DD * HH * DKK;
    if (idx < 3 * per) {
        int which = idx / per;
        int rem   = idx % per;
        int d = rem >> 10;
        int c = rem & 1023;
        int h = c >> 6;
        int k = c & 63;
        const float* W = (which == 0) ? Wq : (which == 1) ? Wk : Wv;
        int kp = (which <= 1) ? ((k & ~7) | perm8(k & 7)) : k;
        g_Wqkv[(size_t)d * N3 + which * 1024 + h * 64 + kp] =
            __uint_as_float(f2tf32(W[h * (DD * DKK) + d * DKK + k]));
    }
    if (idx < N3) {
        int which = idx >> 10;
        int c = idx & 1023;
        int h = c >> 6;
        int k = c & 63;
        int kp = (which <= 1) ? ((k & ~7) | perm8(k & 7)) : k;
        const float* bsrc = (which == 0) ? bq : (which == 1) ? bk : bv;
        g_bqkv[which * 1024 + h * 64 + kp] = bsrc[c];
    }
    if (idx < DD * DOUTT) {
        g_Wo[idx] = __uint_as_float(f2tf32(Wo[idx]));
    }
}

// ============================================================
// Kernel 2: TF32 GEMM, 4-stage cp.async pipeline.
// ============================================================
#define GA_STR 20
#define GB_STR 136
#define G_STAGE_A (128 * GA_STR)
#define G_STAGE_B (16 * GB_STR)
#define GEMM_SMEM_WORDS (4 * (G_STAGE_A + G_STAGE_B))

__global__ __launch_bounds__(256, 2) void gemm_tf32_p4(
    const float* __restrict__ A, const float* __restrict__ Bw,
    const float* __restrict__ bias, float* __restrict__ C,
    int M, int N, int K, int round_out)
{
    extern __shared__ unsigned gsm[];
    unsigned* As = gsm;
    unsigned* Bs = gsm + 4 * G_STAGE_A;

    int tid  = threadIdx.x;
    int lane = tid & 31;
    int w    = tid >> 5;
    int warp_m = w >> 1;
    int warp_n = w & 1;
    int lg = lane >> 2;
    int lq = lane & 3;

    const float* Aptr = A + (size_t)(blockIdx.y * 128) * K;
    const float* Bptr = Bw + blockIdx.x * 128;

    int ar  = tid >> 2;
    int akk = (tid & 3) << 2;
    int bkk = tid >> 5;
    int bn4 = (tid & 31) << 2;

    int ntk = K >> 4;

    #pragma unroll
    for (int ps = 0; ps < 3; ps++) {
        int kt = ps << 4;
        unsigned* Asp = As + ps * G_STAGE_A;
        unsigned* Bsp = Bs + ps * G_STAGE_B;
        cp16(&Asp[ar * GA_STR + akk],        Aptr + (size_t)ar * K + kt + akk);
        cp16(&Asp[(ar + 64) * GA_STR + akk], Aptr + (size_t)(ar + 64) * K + kt + akk);
        cp16(&Bsp[bkk * GB_STR + bn4],       Bptr + (size_t)(kt + bkk) * N + bn4);
        cp16(&Bsp[(bkk + 8) * GB_STR + bn4], Bptr + (size_t)(kt + bkk + 8) * N + bn4);
        CP_COMMIT();
    }

    float acc[2][8][4];
    #pragma unroll
    for (int mt = 0; mt < 2; mt++)
        #pragma unroll
        for (int nt = 0; nt < 8; nt++)
            #pragma unroll
            for (int r = 0; r < 4; r++) acc[mt][nt][r] = 0.0f;

    for (int t = 0; t < ntk; t++) {
        if (t + 3 < ntk) {
            int kt = (t + 3) << 4;
            int ns = (t + 3) & 3;
            unsigned* Asp = As + ns * G_STAGE_A;
            unsigned* Bsp = Bs + ns * G_STAGE_B;
            cp16(&Asp[ar * GA_STR + akk],        Aptr + (size_t)ar * K + kt + akk);
            cp16(&Asp[(ar + 64) * GA_STR + akk], Aptr + (size_t)(ar + 64) * K + kt + akk);
            cp16(&Bsp[bkk * GB_STR + bn4],       Bptr + (size_t)(kt + bkk) * N + bn4);
            cp16(&Bsp[(bkk + 8) * GB_STR + bn4], Bptr + (size_t)(kt + bkk + 8) * N + bn4);
            CP_COMMIT();
        }
        CP_WAIT(2);
        __syncthreads();

        const unsigned* Asl = As + (t & 3) * G_STAGE_A;
        const unsigned* Bsl = Bs + (t & 3) * G_STAGE_B;
        #pragma unroll
        for (int ks = 0; ks < 2; ks++) {
            int k0 = ks * 8;
            unsigned af[2][4];
            #pragma unroll
            for (int mt = 0; mt < 2; mt++) {
                int mb = warp_m * 32 + mt * 16;
                af[mt][0] = Asl[(mb + lg) * GA_STR + k0 + lq];
                af[mt][1] = Asl[(mb + 8 + lg) * GA_STR + k0 + lq];
                af[mt][2] = Asl[(mb + lg) * GA_STR + k0 + 4 + lq];
                af[mt][3] = Asl[(mb + 8 + lg) * GA_STR + k0 + 4 + lq];
            }
            #pragma unroll
            for (int nt = 0; nt < 8; nt++) {
                int nb = warp_n * 64 + nt * 8;
                unsigned b0 = Bsl[(k0 + lq) * GB_STR + nb + lg];
                unsigned b1 = Bsl[(k0 + 4 + lq) * GB_STR + nb + lg];
                #pragma unroll
                for (int mt = 0; mt < 2; mt++)
                    mma_tf32(acc[mt][nt][0], acc[mt][nt][1], acc[mt][nt][2], acc[mt][nt][3],
                             af[mt][0], af[mt][1], af[mt][2], af[mt][3], b0, b1);
            }
        }
        __syncthreads();
    }

    #pragma unroll
    for (int mt = 0; mt < 2; mt++) {
        int row0 = blockIdx.y * 128 + warp_m * 32 + mt * 16 + lg;
        #pragma unroll
        for (int nt = 0; nt < 8; nt++) {
            int col = blockIdx.x * 128 + warp_n * 64 + nt * 8 + 2 * lq;
            float b0 = bias[col], b1 = bias[col + 1];
            float r00 = acc[mt][nt][0] + b0, r01 = acc[mt][nt][1] + b1;
            float r10 = acc[mt][nt][2] + b0, r11 = acc[mt][nt][3] + b1;
            if (round_out) {
                r00 = __uint_as_float(f2tf32(r00));
                r01 = __uint_as_float(f2tf32(r01));
                r10 = __uint_as_float(f2tf32(r10));
                r11 = __uint_as_float(f2tf32(r11));
            }
            *(float2*)(C + (size_t)row0 * N + col) = make_float2(r00, r01);
            *(float2*)(C + (size_t)(row0 + 8) * N + col) = make_float2(r10, r11);
        }
    }
}

// ============================================================
// Kernel 3: flash attention v5.
// block 256 (8 warps), Q tile 256 rows, warp tile 32x64,
// KV 64-key tiles double-buffered. Q/K in pair-permuted dk layout
// (LDS.64 fragments); P staged to smem in permuted layout.
// 1 CTA/SM (216 KB smem).
// ============================================================
#define AQ_STR 72
#define ATT_SMEM_WORDS (256*AQ_STR + 2*64*AQ_STR + 2*64*AQ_STR + 256*AQ_STR)

__global__ __launch_bounds__(256, 1) void attn_tc5(const float* __restrict__ QKV,
                                                   float* __restrict__ cat)
{
    extern __shared__ unsigned sm[];
    unsigned* Qs = sm;                      // [256][72]  (permuted dk)
    unsigned* Ks = sm + 256 * AQ_STR;       // [2][64][72] (permuted dk)
    unsigned* Vs = Ks + 2 * 64 * AQ_STR;    // [2][64][72] (natural dk)
    unsigned* Ps = Vs + 2 * 64 * AQ_STR;    // [256][72]  (permuted t)

    int tid  = threadIdx.x;
    int lane = tid & 31;
    int w    = tid >> 5;          // 0..7
    int lg = lane >> 2;
    int lq = lane & 3;
    int rbase = w * 32;

    int bh = blockIdx.y;
    int b = bh >> 4;
    int h = bh & 15;
    int s0 = blockIdx.x * 256;

    const float* Qbase = QKV + (size_t)(b * SS) * N3 + h * DKK;
    const float* Kbase = Qbase + 1024;
    const float* Vbase = Qbase + 2048;

    int kvr  = tid >> 4;                // 0..15
    int kvc4 = (tid & 15) << 2;

    // prefetch KV tile 0 (64 rows, 16 rows per pass)
    #pragma unroll
    for (int L = 0; L < 4; L++) {
        int r = kvr + L * 16;
        cp16(&Ks[r * AQ_STR + kvc4], Kbase + (size_t)r * N3 + kvc4);
        cp16(&Vs[r * AQ_STR + kvc4], Vbase + (size_t)r * N3 + kvc4);
    }
    CP_COMMIT();

    // load Q tile (256x64 permuted), scale by (1/8)*log2(e), round to tf32
    const float QSC = 0.18033688011112042f;
    #pragma unroll
    for (int L = 0; L < 16; L++) {
        int idx = tid + L * 256;
        int r  = idx >> 4;
        int c4 = (idx & 15) << 2;
        float4 v = *(const float4*)(Qbase + (size_t)(s0 + r) * N3 + c4);
        uint4 o;
        o.x = f2tf32(v.x * QSC);
        o.y = f2tf32(v.y * QSC);
        o.z = f2tf32(v.z * QSC);
        o.w = f2tf32(v.w * QSC);
        *(uint4*)&Qs[r * AQ_STR + c4] = o;
    }

    float o[2][8][4];
    #pragma unroll
    for (int mt = 0; mt < 2; mt++)
        #pragma unroll
        for (int nt = 0; nt < 8; nt++)
            #pragma unroll
            for (int r = 0; r < 4; r++) o[mt][nt][r] = 0.0f;
    float mrun[2][2] = {{-1e30f, -1e30f}, {-1e30f, -1e30f}};
    float lrun[2][2] = {{0.0f, 0.0f}, {0.0f, 0.0f}};

    // P staging positions: feature 2lq -> pos pp, feature 2lq+1 -> pos pp+2
    int pp = perm8(2 * lq);

    const int NT = SS / 64;
    for (int t = 0; t < NT; t++) {
        int st = t & 1;
        if (t + 1 < NT) {
            int kt = (t + 1) * 64;
            unsigned* Kn = Ks + (st ^ 1) * 64 * AQ_STR;
            unsigned* Vn = Vs + (st ^ 1) * 64 * AQ_STR;
            #pragma unroll
            for (int L = 0; L < 4; L++) {
                int r = kvr + L * 16;
                cp16(&Kn[r * AQ_STR + kvc4], Kbase + (size_t)(kt + r) * N3 + kvc4);
                cp16(&Vn[r * AQ_STR + kvc4], Vbase + (size_t)(kt + r) * N3 + kvc4);
            }
            CP_COMMIT();
            CP_WAIT(1);
        } else {
            CP_WAIT(0);
        }
        __syncthreads();

        const unsigned* K_ = Ks + st * 64 * AQ_STR;
        const unsigned* V_ = Vs + st * 64 * AQ_STR;

        // ---- S = Q*K^T : LDS.64 fragments from permuted layout ----
        float s[2][8][4];
        #pragma unroll
        for (int mt = 0; mt < 2; mt++)
            #pragma unroll
            for (int nt = 0; nt < 8; nt++)
                #pragma unroll
                for (int r = 0; r < 4; r++) s[mt][nt][r] = 0.0f;

        #pragma unroll
        for (int ks = 0; ks < 8; ks++) {
            int k0 = ks * 8 + lq * 2;
            unsigned af[2][4];
            #pragma unroll
            for (int mt = 0; mt < 2; mt++) {
                int mb = rbase + mt * 16;
                uint2 qa = *(const uint2*)&Qs[(mb + lg) * AQ_STR + k0];      // {a0,a2}
                uint2 qb = *(const uint2*)&Qs[(mb + 8 + lg) * AQ_STR + k0];  // {a1,a3}
                af[mt][0] = qa.x; af[mt][1] = qb.x; af[mt][2] = qa.y; af[mt][3] = qb.y;
            }
            #pragma unroll
            for (int nt = 0; nt < 8; nt++) {
                uint2 kb = *(const uint2*)&K_[(nt * 8 + lg) * AQ_STR + k0];  // {b0,b1}
                #pragma unroll
                for (int mt = 0; mt < 2; mt++)
                    mma_tf32(s[mt][nt][0], s[mt][nt][1], s[mt][nt][2], s[mt][nt][3],
                             af[mt][0], af[mt][1], af[mt][2], af[mt][3], kb.x, kb.y);
            }
        }

        // ---- online softmax (base 2); stage P into permuted smem ----
        #pragma unroll
        for (int mt = 0; mt < 2; mt++) {
            float mloc0 = -1e30f, mloc1 = -1e30f;
            #pragma unroll
            for (int nt = 0; nt < 8; nt++) {
                mloc0 = fmaxf(mloc0, fmaxf(s[mt][nt][0], s[mt][nt][1]));
                mloc1 = fmaxf(mloc1, fmaxf(s[mt][nt][2], s[mt][nt][3]));
            }
            #pragma unroll
            for (int off = 1; off <= 2; off <<= 1) {
                mloc0 = fmaxf(mloc0, __shfl_xor_sync(0xffffffffu, mloc0, off));
                mloc1 = fmaxf(mloc1, __shfl_xor_sync(0xffffffffu, mloc1, off));
            }
            float mnew0 = fmaxf(mrun[mt][0], mloc0);
            float mnew1 = fmaxf(mrun[mt][1], mloc1);
            float alpha0 = exp2f(mrun[mt][0] - mnew0);
            float alpha1 = exp2f(mrun[mt][1] - mnew1);

            int mb = rbase + mt * 16;
            float rs0 = 0.0f, rs1 = 0.0f;
            #pragma unroll
            for (int nt = 0; nt < 8; nt++) {
                float p0 = exp2f(s[mt][nt][0] - mnew0);
                float p1 = exp2f(s[mt][nt][1] - mnew0);
                float p2 = exp2f(s[mt][nt][2] - mnew1);
                float p3 = exp2f(s[mt][nt][3] - mnew1);
                rs0 += p0 + p1;
                rs1 += p2 + p3;
                int base0 = (mb + lg) * AQ_STR + nt * 8;
                int base1 = (mb + 8 + lg) * AQ_STR + nt * 8;
                Ps[base0 + pp]     = f2tf32(p0);
                Ps[base0 + pp + 2] = f2tf32(p1);
                Ps[base1 + pp]     = f2tf32(p2);
                Ps[base1 + pp + 2] = f2tf32(p3);
            }
            #pragma unroll
            for (int off = 1; off <= 2; off <<= 1) {
                rs0 += __shfl_xor_sync(0xffffffffu, rs0, off);
                rs1 += __shfl_xor_sync(0xffffffffu, rs1, off);
            }
            lrun[mt][0] = lrun[mt][0] * alpha0 + rs0;
            lrun[mt][1] = lrun[mt][1] * alpha1 + rs1;
            mrun[mt][0] = mnew0;
            mrun[mt][1] = mnew1;
            #pragma unroll
            for (int nt = 0; nt < 8; nt++) {
                o[mt][nt][0] *= alpha0; o[mt][nt][1] *= alpha0;
                o[mt][nt][2] *= alpha1; o[mt][nt][3] *= alpha1;
            }
        }
        __syncwarp();   // P rows are warp-private

        // ---- O += P*V : P A-frags via LDS.64 (permuted), V scalar ----
        #pragma unroll
        for (int ks = 0; ks < 8; ks++) {
            int k0 = ks * 8 + lq * 2;
            unsigned af[2][4];
            #pragma unroll
            for (int mt = 0; mt < 2; mt++) {
                int mb = rbase + mt * 16;
                uint2 pa = *(const uint2*)&Ps[(mb + lg) * AQ_STR + k0];
                uint2 pb = *(const uint2*)&Ps[(mb + 8 + lg) * AQ_STR + k0];
                af[mt][0] = pa.x; af[mt][1] = pb.x; af[mt][2] = pa.y; af[mt][3] = pb.y;
            }
            int kr = ks * 8;
            #pragma unroll
            for (int nt = 0; nt < 8; nt++) {
                unsigned b0 = V_[(kr + lq) * AQ_STR + nt * 8 + lg];
                unsigned b1 = V_[(kr + 4 + lq) * AQ_STR + nt * 8 + lg];
                #pragma unroll
                for (int mt = 0; mt < 2; mt++)
                    mma_tf32(o[mt][nt][0], o[mt][nt][1], o[mt][nt][2], o[mt][nt][3],
                             af[mt][0], af[mt][1], af[mt][2], af[mt][3], b0, b1);
            }
        }
        __syncthreads();
    }

    // epilogue (natural dk order — V was natural)
    #pragma unroll
    for (int mt = 0; mt < 2; mt++) {
        float inv0 = 1.0f / lrun[mt][0];
        float inv1 = 1.0f / lrun[mt][1];
        int row = s0 + rbase + mt * 16 + lg;
        #pragma unroll
        for (int nt = 0; nt < 8; nt++) {
            int col = h * DKK + nt * 8 + 2 * lq;
            float2 v0 = make_float2(__uint_as_float(f2tf32(o[mt][nt][0] * inv0)),
                                    __uint_as_float(f2tf32(o[mt][nt][1] * inv0)));
            float2 v1 = make_float2(__uint_as_float(f2tf32(o[mt][nt][2] * inv1)),
                                    __uint_as_float(f2tf32(o[mt][nt][3] * inv1)));
            *(float2*)(cat + (size_t)(b * SS + row) * DOUTT + col) = v0;
            *(float2*)(cat + (size_t)(b * SS + row + 8) * DOUTT + col) = v1;
        }
    }
}

// ============================================================
// launch
// ============================================================
extern "C" void kernel_launch(void* const* d_in, const int* in_sizes, int n_in,
                              void* d_out, int out_size) {
    const float* x  = (const float*)d_in[0];
    const float* Wq = (const float*)d_in[1];
    const float* bq = (const float*)d_in[2];
    const float* Wk = (const float*)d_in[3];
    const float* bk = (const float*)d_in[4];
    const float* Wv = (const float*)d_in[5];
    const float* bv = (const float*)d_in[6];
    const float* Wo = (const float*)d_in[7];
    const float* bo = (const float*)d_in[8];
    float* out = (float*)d_out;

    float *pWqkv, *pbqkv, *pWo, *pxr, *pQKV, *pcat;
    cudaGetSymbolAddress((void**)&pWqkv, g_Wqkv);
    cudaGetSymbolAddress((void**)&pbqkv, g_bqkv);
    cudaGetSymbolAddress((void**)&pWo,   g_Wo);
    cudaGetSymbolAddress((void**)&pxr,   g_xr);
    cudaGetSymbolAddress((void**)&pQKV,  g_QKV);
    cudaGetSymbolAddress((void**)&pcat,  g_cat);

    {
        int n4 = MM * DD / 4;
        round_x_kernel<<<(n4 + 255) / 256, 256>>>(x);
    }
    {
        int total = 3 * DD * HH * DKK;
        pack_weights_kernel<<<(total + 255) / 256, 256>>>(Wq, bq, Wk, bk, Wv, bv, Wo);
    }
    {
        cudaFuncSetAttribute(gemm_tf32_p4, cudaFuncAttributeMaxDynamicSharedMemorySize,
                             GEMM_SMEM_WORDS * (int)sizeof(unsigned));
        dim3 grid(N3 / 128, MM / 128);
        gemm_tf32_p4<<<grid, 256, GEMM_SMEM_WORDS * sizeof(unsigned)>>>(
            pxr, pWqkv, pbqkv, pQKV, MM, N3, DD, 1);
    }
    {
        cudaFuncSetAttribute(attn_tc5, cudaFuncAttributeMaxDynamicSharedMemorySize,
                             ATT_SMEM_WORDS * (int)sizeof(unsigned));
        dim3 grid(SS / 256, BB * HH);
        attn_tc5<<<grid, 256, ATT_SMEM_WORDS * sizeof(unsigned)>>>(pQKV, pcat);
    }
    {
        dim3 grid(DOUTT / 128, MM / 128);
        gemm_tf32_p4<<<grid, 256, GEMM_SMEM_WORDS * sizeof(unsigned)>>>(
            pcat, pWo, bo, out, MM, DOUTT, DD, 0);
    }
}

// round 9
// speedup vs baseline: 1.1435x; 1.1435x over previous
#include <cuda_runtime.h>
#include <math.h>
#include <stdint.h>

#define BB   4
#define SS   2048
#define DD   1024
#define HH   16
#define DKK  64
#define DOUTT 1024
#define MM   (BB*SS)
#define N3   (3*HH*DKK)

// -------- scratch --------
__device__ float g_Wqkv[DD * N3];
__device__ float g_bqkv[N3];
__device__ float g_Wo[DD * DOUTT];
__device__ float g_xr[(size_t)MM * DD];
__device__ float g_QKV[(size_t)MM * N3];
__device__ float g_cat[(size_t)MM * DOUTT];

__device__ __forceinline__ unsigned f2tf32(float x) {
    unsigned r;
    asm("cvt.rna.tf32.f32 %0, %1;" : "=r"(r) : "f"(x));
    return r;
}

__device__ __forceinline__ void mma_tf32(float& c0, float& c1, float& c2, float& c3,
                                         unsigned a0, unsigned a1, unsigned a2, unsigned a3,
                                         unsigned b0, unsigned b1) {
    asm volatile(
        "mma.sync.aligned.m16n8k8.row.col.f32.tf32.tf32.f32 "
        "{%0,%1,%2,%3}, {%4,%5,%6,%7}, {%8,%9}, {%0,%1,%2,%3};\n"
        : "+f"(c0), "+f"(c1), "+f"(c2), "+f"(c3)
        : "r"(a0), "r"(a1), "r"(a2), "r"(a3), "r"(b0), "r"(b1));
}

__device__ __forceinline__ void cp16(unsigned* smem_ptr, const float* gmem_ptr) {
    unsigned dst = (unsigned)__cvta_generic_to_shared(smem_ptr);
    asm volatile("cp.async.cg.shared.global [%0], [%1], 16;\n" :: "r"(dst), "l"(gmem_ptr));
}
#define CP_COMMIT() asm volatile("cp.async.commit_group;\n" ::: "memory")
#define CP_WAIT(n)  asm volatile("cp.async.wait_group %0;\n" :: "n"(n) : "memory")

// within-8 pair permutation: feature j goes to position (j&3)*2 + (j>>2)
__host__ __device__ __forceinline__ int perm8(int j) {
    return ((j & 3) << 1) | (j >> 2);
}

// ============================================================
// Kernel 0: round x to tf32 grid
// ============================================================
__global__ void round_x_kernel(const float* __restrict__ x) {
    size_t i = (size_t)(blockIdx.x * blockDim.x + threadIdx.x) * 4;
    if (i < (size_t)MM * DD) {
        float4 v = *(const float4*)(x + i);
        float4 o;
        o.x = __uint_as_float(f2tf32(v.x));
        o.y = __uint_as_float(f2tf32(v.y));
        o.z = __uint_as_float(f2tf32(v.z));
        o.w = __uint_as_float(f2tf32(v.w));
        *(float4*)(g_xr + i) = o;
    }
}

// ============================================================
// Kernel 1: pack+round weights. Q,K head-dk columns stored
// PAIR-PERMUTED (per 8-block) -> attention LDS.64 fragments.
// V and Wo natural.
// ============================================================
__global__ void pack_weights_kernel(const float* __restrict__ Wq,
                                    const float* __restrict__ bq,
                                    const float* __restrict__ Wk,
                                    const float* __restrict__ bk,
                                    const float* __restrict__ Wv,
                                    const float* __restrict__ bv,
                                    const float* __restrict__ Wo) {
    int idx = blockIdx.x * blockDim.x + threadIdx.x;
    const int per = DD * HH * DKK;
    if (idx < 3 * per) {
        int which = idx / per;
        int rem   = idx % per;
        int d = rem >> 10;
        int c = rem & 1023;
        int h = c >> 6;
        int k = c & 63;
        const float* W = (which == 0) ? Wq : (which == 1) ? Wk : Wv;
        int kp = (which <= 1) ? ((k & ~7) | perm8(k & 7)) : k;
        g_Wqkv[(size_t)d * N3 + which * 1024 + h * 64 + kp] =
            __uint_as_float(f2tf32(W[h * (DD * DKK) + d * DKK + k]));
    }
    if (idx < N3) {
        int which = idx >> 10;
        int c = idx & 1023;
        int h = c >> 6;
        int k = c & 63;
        int kp = (which <= 1) ? ((k & ~7) | perm8(k & 7)) : k;
        const float* bsrc = (which == 0) ? bq : (which == 1) ? bk : bv;
        g_bqkv[which * 1024 + h * 64 + kp] = bsrc[c];
    }
    if (idx < DD * DOUTT) {
        g_Wo[idx] = __uint_as_float(f2tf32(Wo[idx]));
    }
}

// ============================================================
// Kernel 2: TF32 GEMM, 4-stage cp.async pipeline (unchanged).
// ============================================================
#define GA_STR 20
#define GB_STR 136
#define G_STAGE_A (128 * GA_STR)
#define G_STAGE_B (16 * GB_STR)
#define GEMM_SMEM_WORDS (4 * (G_STAGE_A + G_STAGE_B))

__global__ __launch_bounds__(256, 2) void gemm_tf32_p4(
    const float* __restrict__ A, const float* __restrict__ Bw,
    const float* __restrict__ bias, float* __restrict__ C,
    int M, int N, int K, int round_out)
{
    extern __shared__ unsigned gsm[];
    unsigned* As = gsm;
    unsigned* Bs = gsm + 4 * G_STAGE_A;

    int tid  = threadIdx.x;
    int lane = tid & 31;
    int w    = tid >> 5;
    int warp_m = w >> 1;
    int warp_n = w & 1;
    int lg = lane >> 2;
    int lq = lane & 3;

    const float* Aptr = A + (size_t)(blockIdx.y * 128) * K;
    const float* Bptr = Bw + blockIdx.x * 128;

    int ar  = tid >> 2;
    int akk = (tid & 3) << 2;
    int bkk = tid >> 5;
    int bn4 = (tid & 31) << 2;

    int ntk = K >> 4;

    #pragma unroll
    for (int ps = 0; ps < 3; ps++) {
        int kt = ps << 4;
        unsigned* Asp = As + ps * G_STAGE_A;
        unsigned* Bsp = Bs + ps * G_STAGE_B;
        cp16(&Asp[ar * GA_STR + akk],        Aptr + (size_t)ar * K + kt + akk);
        cp16(&Asp[(ar + 64) * GA_STR + akk], Aptr + (size_t)(ar + 64) * K + kt + akk);
        cp16(&Bsp[bkk * GB_STR + bn4],       Bptr + (size_t)(kt + bkk) * N + bn4);
        cp16(&Bsp[(bkk + 8) * GB_STR + bn4], Bptr + (size_t)(kt + bkk + 8) * N + bn4);
        CP_COMMIT();
    }

    float acc[2][8][4];
    #pragma unroll
    for (int mt = 0; mt < 2; mt++)
        #pragma unroll
        for (int nt = 0; nt < 8; nt++)
            #pragma unroll
            for (int r = 0; r < 4; r++) acc[mt][nt][r] = 0.0f;

    for (int t = 0; t < ntk; t++) {
        if (t + 3 < ntk) {
            int kt = (t + 3) << 4;
            int ns = (t + 3) & 3;
            unsigned* Asp = As + ns * G_STAGE_A;
            unsigned* Bsp = Bs + ns * G_STAGE_B;
            cp16(&Asp[ar * GA_STR + akk],        Aptr + (size_t)ar * K + kt + akk);
            cp16(&Asp[(ar + 64) * GA_STR + akk], Aptr + (size_t)(ar + 64) * K + kt + akk);
            cp16(&Bsp[bkk * GB_STR + bn4],       Bptr + (size_t)(kt + bkk) * N + bn4);
            cp16(&Bsp[(bkk + 8) * GB_STR + bn4], Bptr + (size_t)(kt + bkk + 8) * N + bn4);
            CP_COMMIT();
        }
        CP_WAIT(2);
        __syncthreads();

        const unsigned* Asl = As + (t & 3) * G_STAGE_A;
        const unsigned* Bsl = Bs + (t & 3) * G_STAGE_B;
        #pragma unroll
        for (int ks = 0; ks < 2; ks++) {
            int k0 = ks * 8;
            unsigned af[2][4];
            #pragma unroll
            for (int mt = 0; mt < 2; mt++) {
                int mb = warp_m * 32 + mt * 16;
                af[mt][0] = Asl[(mb + lg) * GA_STR + k0 + lq];
                af[mt][1] = Asl[(mb + 8 + lg) * GA_STR + k0 + lq];
                af[mt][2] = Asl[(mb + lg) * GA_STR + k0 + 4 + lq];
                af[mt][3] = Asl[(mb + 8 + lg) * GA_STR + k0 + 4 + lq];
            }
            #pragma unroll
            for (int nt = 0; nt < 8; nt++) {
                int nb = warp_n * 64 + nt * 8;
                unsigned b0 = Bsl[(k0 + lq) * GB_STR + nb + lg];
                unsigned b1 = Bsl[(k0 + 4 + lq) * GB_STR + nb + lg];
                #pragma unroll
                for (int mt = 0; mt < 2; mt++)
                    mma_tf32(acc[mt][nt][0], acc[mt][nt][1], acc[mt][nt][2], acc[mt][nt][3],
                             af[mt][0], af[mt][1], af[mt][2], af[mt][3], b0, b1);
            }
        }
        __syncthreads();
    }

    #pragma unroll
    for (int mt = 0; mt < 2; mt++) {
        int row0 = blockIdx.y * 128 + warp_m * 32 + mt * 16 + lg;
        #pragma unroll
        for (int nt = 0; nt < 8; nt++) {
            int col = blockIdx.x * 128 + warp_n * 64 + nt * 8 + 2 * lq;
            float b0 = bias[col], b1 = bias[col + 1];
            float r00 = acc[mt][nt][0] + b0, r01 = acc[mt][nt][1] + b1;
            float r10 = acc[mt][nt][2] + b0, r11 = acc[mt][nt][3] + b1;
            if (round_out) {
                r00 = __uint_as_float(f2tf32(r00));
                r01 = __uint_as_float(f2tf32(r01));
                r10 = __uint_as_float(f2tf32(r10));
                r11 = __uint_as_float(f2tf32(r11));
            }
            *(float2*)(C + (size_t)row0 * N + col) = make_float2(r00, r01);
            *(float2*)(C + (size_t)(row0 + 8) * N + col) = make_float2(r10, r11);
        }
    }
}

// ============================================================
// Kernel 3: flash attention v6 = v4 config + permuted LDS.64 S-frags.
// block 128 (4 warps), Q tile 128 rows, warp tile 32x64 (2 m-tiles),
// KV 64-key tiles double-buffered, P via register shuffles.
// stride 72: V-loads conflict-free too. 2 CTAs/SM.
// ============================================================
#define AQ_STR 72
#define ATT_SMEM_WORDS (128*AQ_STR + 2*64*AQ_STR + 2*64*AQ_STR)   // 27648 w = 110592 B

__global__ __launch_bounds__(128, 2) void attn_tc6(const float* __restrict__ QKV,
                                                   float* __restrict__ cat)
{
    extern __shared__ unsigned sm[];
    unsigned* Qs = sm;                    // [128][72]  (permuted dk)
    unsigned* Ks = sm + 128 * AQ_STR;     // [2][64][72] (permuted dk)
    unsigned* Vs = Ks + 2 * 64 * AQ_STR;  // [2][64][72] (natural dk)

    int tid  = threadIdx.x;
    int lane = tid & 31;
    int w    = tid >> 5;          // 0..3
    int lg = lane >> 2;
    int lq = lane & 3;
    int rbase = w * 32;

    int bh = blockIdx.y;
    int b = bh >> 4;
    int h = bh & 15;
    int s0 = blockIdx.x * 128;

    const float* Qbase = QKV + (size_t)(b * SS) * N3 + h * DKK;
    const float* Kbase = Qbase + 1024;
    const float* Vbase = Qbase + 2048;

    int kvr  = tid >> 4;                // 0..7
    int kvc4 = (tid & 15) << 2;

    // prefetch KV tile 0 (64 rows, 8 rows per pass)
    #pragma unroll
    for (int L = 0; L < 8; L++) {
        int r = kvr + L * 8;
        cp16(&Ks[r * AQ_STR + kvc4], Kbase + (size_t)r * N3 + kvc4);
        cp16(&Vs[r * AQ_STR + kvc4], Vbase + (size_t)r * N3 + kvc4);
    }
    CP_COMMIT();

    // load Q tile (128x64, already permuted in gmem), scale by (1/8)*log2(e)
    const float QSC = 0.18033688011112042f;
    #pragma unroll
    for (int L = 0; L < 16; L++) {
        int idx = tid + L * 128;
        int r  = idx >> 4;
        int c4 = (idx & 15) << 2;
        float4 v = *(const float4*)(Qbase + (size_t)(s0 + r) * N3 + c4);
        uint4 o;
        o.x = f2tf32(v.x * QSC);
        o.y = f2tf32(v.y * QSC);
        o.z = f2tf32(v.z * QSC);
        o.w = f2tf32(v.w * QSC);
        *(uint4*)&Qs[r * AQ_STR + c4] = o;
    }

    float o[2][8][4];
    #pragma unroll
    for (int mt = 0; mt < 2; mt++)
        #pragma unroll
        for (int nt = 0; nt < 8; nt++)
            #pragma unroll
            for (int r = 0; r < 4; r++) o[mt][nt][r] = 0.0f;
    float mrun[2][2] = {{-1e30f, -1e30f}, {-1e30f, -1e30f}};
    float lrun[2][2] = {{0.0f, 0.0f}, {0.0f, 0.0f}};

    // shuffle source lanes for S->A fragment conversion
    int L0 = (lane & ~3) | (lq >> 1);
    int L1 = L0 + 2;
    bool sel = (lq & 1);

    const int NT = SS / 64;
    for (int t = 0; t < NT; t++) {
        int st = t & 1;
        if (t + 1 < NT) {
            int kt = (t + 1) * 64;
            unsigned* Kn = Ks + (st ^ 1) * 64 * AQ_STR;
            unsigned* Vn = Vs + (st ^ 1) * 64 * AQ_STR;
            #pragma unroll
            for (int L = 0; L < 8; L++) {
                int r = kvr + L * 8;
                cp16(&Kn[r * AQ_STR + kvc4], Kbase + (size_t)(kt + r) * N3 + kvc4);
                cp16(&Vn[r * AQ_STR + kvc4], Vbase + (size_t)(kt + r) * N3 + kvc4);
            }
            CP_COMMIT();
            CP_WAIT(1);
        } else {
            CP_WAIT(0);
        }
        __syncthreads();

        const unsigned* K_ = Ks + st * 64 * AQ_STR;
        const unsigned* V_ = Vs + st * 64 * AQ_STR;

        // ---- S = Q*K^T : LDS.64 fragments from permuted layout ----
        float s[2][8][4];
        #pragma unroll
        for (int mt = 0; mt < 2; mt++)
            #pragma unroll
            for (int nt = 0; nt < 8; nt++)
                #pragma unroll
                for (int r = 0; r < 4; r++) s[mt][nt][r] = 0.0f;

        #pragma unroll
        for (int ks = 0; ks < 8; ks++) {
            int k0 = ks * 8 + lq * 2;
            unsigned af[2][4];
            #pragma unroll
            for (int mt = 0; mt < 2; mt++) {
                int mb = rbase + mt * 16;
                uint2 qa = *(const uint2*)&Qs[(mb + lg) * AQ_STR + k0];      // {a0,a2}
                uint2 qb = *(const uint2*)&Qs[(mb + 8 + lg) * AQ_STR + k0];  // {a1,a3}
                af[mt][0] = qa.x; af[mt][1] = qb.x; af[mt][2] = qa.y; af[mt][3] = qb.y;
            }
            #pragma unroll
            for (int nt = 0; nt < 8; nt++) {
                uint2 kb = *(const uint2*)&K_[(nt * 8 + lg) * AQ_STR + k0];  // {b0,b1}
                #pragma unroll
                for (int mt = 0; mt < 2; mt++)
                    mma_tf32(s[mt][nt][0], s[mt][nt][1], s[mt][nt][2], s[mt][nt][3],
                             af[mt][0], af[mt][1], af[mt][2], af[mt][3], kb.x, kb.y);
            }
        }

        // ---- online softmax (base 2), per m-tile; convert P to tf32 ----
        #pragma unroll
        for (int mt = 0; mt < 2; mt++) {
            float mloc0 = -1e30f, mloc1 = -1e30f;
            #pragma unroll
            for (int nt = 0; nt < 8; nt++) {
                mloc0 = fmaxf(mloc0, fmaxf(s[mt][nt][0], s[mt][nt][1]));
                mloc1 = fmaxf(mloc1, fmaxf(s[mt][nt][2], s[mt][nt][3]));
            }
            #pragma unroll
            for (int off = 1; off <= 2; off <<= 1) {
                mloc0 = fmaxf(mloc0, __shfl_xor_sync(0xffffffffu, mloc0, off));
                mloc1 = fmaxf(mloc1, __shfl_xor_sync(0xffffffffu, mloc1, off));
            }
            float mnew0 = fmaxf(mrun[mt][0], mloc0);
            float mnew1 = fmaxf(mrun[mt][1], mloc1);
            float alpha0 = exp2f(mrun[mt][0] - mnew0);
            float alpha1 = exp2f(mrun[mt][1] - mnew1);

            float rs0 = 0.0f, rs1 = 0.0f;
            #pragma unroll
            for (int nt = 0; nt < 8; nt++) {
                float p0 = exp2f(s[mt][nt][0] - mnew0);
                float p1 = exp2f(s[mt][nt][1] - mnew0);
                float p2 = exp2f(s[mt][nt][2] - mnew1);
                float p3 = exp2f(s[mt][nt][3] - mnew1);
                rs0 += p0 + p1;
                rs1 += p2 + p3;
                s[mt][nt][0] = __uint_as_float(f2tf32(p0));
                s[mt][nt][1] = __uint_as_float(f2tf32(p1));
                s[mt][nt][2] = __uint_as_float(f2tf32(p2));
                s[mt][nt][3] = __uint_as_float(f2tf32(p3));
            }
            #pragma unroll
            for (int off = 1; off <= 2; off <<= 1) {
                rs0 += __shfl_xor_sync(0xffffffffu, rs0, off);
                rs1 += __shfl_xor_sync(0xffffffffu, rs1, off);
            }
            lrun[mt][0] = lrun[mt][0] * alpha0 + rs0;
            lrun[mt][1] = lrun[mt][1] * alpha1 + rs1;
            mrun[mt][0] = mnew0;
            mrun[mt][1] = mnew1;
            #pragma unroll
            for (int nt = 0; nt < 8; nt++) {
                o[mt][nt][0] *= alpha0; o[mt][nt][1] *= alpha0;
                o[mt][nt][2] *= alpha1; o[mt][nt][3] *= alpha1;
            }
        }

        // ---- O += P*V : P A-fragments via shuffles; V frags shared over mt ----
        #pragma unroll
        for (int ks = 0; ks < 8; ks++) {
            unsigned af[2][4];
            #pragma unroll
            for (int mt = 0; mt < 2; mt++) {
                unsigned p0 = __float_as_uint(s[mt][ks][0]);
                unsigned p1 = __float_as_uint(s[mt][ks][1]);
                unsigned p2 = __float_as_uint(s[mt][ks][2]);
                unsigned p3 = __float_as_uint(s[mt][ks][3]);
                unsigned t00 = __shfl_sync(0xffffffffu, p0, L0);
                unsigned t01 = __shfl_sync(0xffffffffu, p1, L0);
                unsigned t02 = __shfl_sync(0xffffffffu, p2, L0);
                unsigned t03 = __shfl_sync(0xffffffffu, p3, L0);
                unsigned t10 = __shfl_sync(0xffffffffu, p0, L1);
                unsigned t11 = __shfl_sync(0xffffffffu, p1, L1);
                unsigned t12 = __shfl_sync(0xffffffffu, p2, L1);
                unsigned t13 = __shfl_sync(0xffffffffu, p3, L1);
                af[mt][0] = sel ? t01 : t00;
                af[mt][1] = sel ? t03 : t02;
                af[mt][2] = sel ? t11 : t10;
                af[mt][3] = sel ? t13 : t12;
            }
            int k0 = ks * 8;
            #pragma unroll
            for (int nt = 0; nt < 8; nt++) {
                unsigned b0 = V_[(k0 + lq) * AQ_STR + nt * 8 + lg];
                unsigned b1 = V_[(k0 + 4 + lq) * AQ_STR + nt * 8 + lg];
                #pragma unroll
                for (int mt = 0; mt < 2; mt++)
                    mma_tf32(o[mt][nt][0], o[mt][nt][1], o[mt][nt][2], o[mt][nt][3],
                             af[mt][0], af[mt][1], af[mt][2], af[mt][3], b0, b1);
            }
        }
        __syncthreads();
    }

    // epilogue (natural dk order — V was natural)
    #pragma unroll
    for (int mt = 0; mt < 2; mt++) {
        float inv0 = 1.0f / lrun[mt][0];
        float inv1 = 1.0f / lrun[mt][1];
        int row = s0 + rbase + mt * 16 + lg;
        #pragma unroll
        for (int nt = 0; nt < 8; nt++) {
            int col = h * DKK + nt * 8 + 2 * lq;
            float2 v0 = make_float2(__uint_as_float(f2tf32(o[mt][nt][0] * inv0)),
                                    __uint_as_float(f2tf32(o[mt][nt][1] * inv0)));
            float2 v1 = make_float2(__uint_as_float(f2tf32(o[mt][nt][2] * inv1)),
                                    __uint_as_float(f2tf32(o[mt][nt][3] * inv1)));
            *(float2*)(cat + (size_t)(b * SS + row) * DOUTT + col) = v0;
            *(float2*)(cat + (size_t)(b * SS + row + 8) * DOUTT + col) = v1;
        }
    }
}

// ============================================================
// launch
// ============================================================
extern "C" void kernel_launch(void* const* d_in, const int* in_sizes, int n_in,
                              void* d_out, int out_size) {
    const float* x  = (const float*)d_in[0];
    const float* Wq = (const float*)d_in[1];
    const float* bq = (const float*)d_in[2];
    const float* Wk = (const float*)d_in[3];
    const float* bk = (const float*)d_in[4];
    const float* Wv = (const float*)d_in[5];
    const float* bv = (const float*)d_in[6];
    const float* Wo = (const float*)d_in[7];
    const float* bo = (const float*)d_in[8];
    float* out = (float*)d_out;

    float *pWqkv, *pbqkv, *pWo, *pxr, *pQKV, *pcat;
    cudaGetSymbolAddress((void**)&pWqkv, g_Wqkv);
    cudaGetSymbolAddress((void**)&pbqkv, g_bqkv);
    cudaGetSymbolAddress((void**)&pWo,   g_Wo);
    cudaGetSymbolAddress((void**)&pxr,   g_xr);
    cudaGetSymbolAddress((void**)&pQKV,  g_QKV);
    cudaGetSymbolAddress((void**)&pcat,  g_cat);

    {
        int n4 = MM * DD / 4;
        round_x_kernel<<<(n4 + 255) / 256, 256>>>(x);
    }
    {
        int total = 3 * DD * HH * DKK;
        pack_weights_kernel<<<(total + 255) / 256, 256>>>(Wq, bq, Wk, bk, Wv, bv, Wo);
    }
    {
        cudaFuncSetAttribute(gemm_tf32_p4, cudaFuncAttributeMaxDynamicSharedMemorySize,
                             GEMM_SMEM_WORDS * (int)sizeof(unsigned));
        dim3 grid(N3 / 128, MM / 128);
        gemm_tf32_p4<<<grid, 256, GEMM_SMEM_WORDS * sizeof(unsigned)>>>(
            pxr, pWqkv, pbqkv, pQKV, MM, N3, DD, 1);
    }
    {
        cudaFuncSetAttribute(attn_tc6, cudaFuncAttributeMaxDynamicSharedMemorySize,
                             ATT_SMEM_WORDS * (int)sizeof(unsigned));
        dim3 grid(SS / 128, BB * HH);
        attn_tc6<<<grid, 128, ATT_SMEM_WORDS * sizeof(unsigned)>>>(pQKV, pcat);
    }
    {
        dim3 grid(DOUTT / 128, MM / 128);
        gemm_tf32_p4<<<grid, 256, GEMM_SMEM_WORDS * sizeof(unsigned)>>>(
            pcat, pWo, bo, out, MM, DOUTT, DD, 0);
    }
}

// round 10
// speedup vs baseline: 1.2224x; 1.0690x over previous
#include <cuda_runtime.h>
#include <math.h>
#include <stdint.h>

#define BB   4
#define SS   2048
#define DD   1024
#define HH   16
#define DKK  64
#define DOUTT 1024
#define MM   (BB*SS)
#define N3   (3*HH*DKK)

// -------- scratch --------
__device__ float g_Wqkv[DD * N3];
__device__ float g_bqkv[N3];
__device__ float g_Wo[DD * DOUTT];
__device__ float g_xr[(size_t)MM * DD];
__device__ float g_QKV[(size_t)MM * N3];
__device__ float g_cat[(size_t)MM * DOUTT];

__device__ __forceinline__ unsigned f2tf32(float x) {
    unsigned r;
    asm("cvt.rna.tf32.f32 %0, %1;" : "=r"(r) : "f"(x));
    return r;
}

__device__ __forceinline__ float ex2(float x) {
    float y;
    asm("ex2.approx.ftz.f32 %0, %1;" : "=f"(y) : "f"(x));
    return y;
}

__device__ __forceinline__ void mma_tf32(float& c0, float& c1, float& c2, float& c3,
                                         unsigned a0, unsigned a1, unsigned a2, unsigned a3,
                                         unsigned b0, unsigned b1) {
    asm volatile(
        "mma.sync.aligned.m16n8k8.row.col.f32.tf32.tf32.f32 "
        "{%0,%1,%2,%3}, {%4,%5,%6,%7}, {%8,%9}, {%0,%1,%2,%3};\n"
        : "+f"(c0), "+f"(c1), "+f"(c2), "+f"(c3)
        : "r"(a0), "r"(a1), "r"(a2), "r"(a3), "r"(b0), "r"(b1));
}

__device__ __forceinline__ void cp16(unsigned* smem_ptr, const float* gmem_ptr) {
    unsigned dst = (unsigned)__cvta_generic_to_shared(smem_ptr);
    asm volatile("cp.async.cg.shared.global [%0], [%1], 16;\n" :: "r"(dst), "l"(gmem_ptr));
}
#define CP_COMMIT() asm volatile("cp.async.commit_group;\n" ::: "memory")
#define CP_WAIT(n)  asm volatile("cp.async.wait_group %0;\n" :: "n"(n) : "memory")

// within-8 pair permutation: feature j goes to position (j&3)*2 + (j>>2)
__host__ __device__ __forceinline__ int perm8(int j) {
    return ((j & 3) << 1) | (j >> 2);
}

// ============================================================
// Kernel 0: round x to tf32 grid
// ============================================================
__global__ void round_x_kernel(const float* __restrict__ x) {
    size_t i = (size_t)(blockIdx.x * blockDim.x + threadIdx.x) * 4;
    if (i < (size_t)MM * DD) {
        float4 v = *(const float4*)(x + i);
        float4 o;
        o.x = __uint_as_float(f2tf32(v.x));
        o.y = __uint_as_float(f2tf32(v.y));
        o.z = __uint_as_float(f2tf32(v.z));
        o.w = __uint_as_float(f2tf32(v.w));
        *(float4*)(g_xr + i) = o;
    }
}

// ============================================================
// Kernel 1: pack+round weights. Q,K head-dk columns stored
// PAIR-PERMUTED (per 8-block) -> attention LDS.64 fragments.
// ============================================================
__global__ void pack_weights_kernel(const float* __restrict__ Wq,
                                    const float* __restrict__ bq,
                                    const float* __restrict__ Wk,
                                    const float* __restrict__ bk,
                                    const float* __restrict__ Wv,
                                    const float* __restrict__ bv,
                                    const float* __restrict__ Wo) {
    int idx = blockIdx.x * blockDim.x + threadIdx.x;
    const int per = DD * HH * DKK;
    if (idx < 3 * per) {
        int which = idx / per;
        int rem   = idx % per;
        int d = rem >> 10;
        int c = rem & 1023;
        int h = c >> 6;
        int k = c & 63;
        const float* W = (which == 0) ? Wq : (which == 1) ? Wk : Wv;
        int kp = (which <= 1) ? ((k & ~7) | perm8(k & 7)) : k;
        g_Wqkv[(size_t)d * N3 + which * 1024 + h * 64 + kp] =
            __uint_as_float(f2tf32(W[h * (DD * DKK) + d * DKK + k]));
    }
    if (idx < N3) {
        int which = idx >> 10;
        int c = idx & 1023;
        int h = c >> 6;
        int k = c & 63;
        int kp = (which <= 1) ? ((k & ~7) | perm8(k & 7)) : k;
        const float* bsrc = (which == 0) ? bq : (which == 1) ? bk : bv;
        g_bqkv[which * 1024 + h * 64 + kp] = bsrc[c];
    }
    if (idx < DD * DOUTT) {
        g_Wo[idx] = __uint_as_float(f2tf32(Wo[idx]));
    }
}

// ============================================================
// Kernel 2: TF32 GEMM, BK=32, 3-stage cp.async pipeline.
// block 256 (8 warps), tile 128x128, warp 32x64. 2 CTAs/SM.
// ============================================================
#define GA2 36    // 36 mod 32 = 4 -> A frag lanes hit distinct banks
#define GB2 136   // 136 mod 32 = 8 -> B frag conflict-free
#define G2_STAGE_A (128 * GA2)   // 4608
#define G2_STAGE_B (32 * GB2)    // 4352
#define GEMM_SMEM_WORDS (3 * (G2_STAGE_A + G2_STAGE_B))   // 26880 w = 107520 B

__global__ __launch_bounds__(256, 2) void gemm_tf32_b32(
    const float* __restrict__ A, const float* __restrict__ Bw,
    const float* __restrict__ bias, float* __restrict__ C,
    int M, int N, int K, int round_out)
{
    extern __shared__ unsigned gsm[];
    unsigned* As = gsm;                    // [3][128*GA2]
    unsigned* Bs = gsm + 3 * G2_STAGE_A;   // [3][32*GB2]

    int tid  = threadIdx.x;
    int lane = tid & 31;
    int w    = tid >> 5;
    int warp_m = w >> 1;
    int warp_n = w & 1;
    int lg = lane >> 2;
    int lq = lane & 3;

    const float* Aptr = A + (size_t)(blockIdx.y * 128) * K;
    const float* Bptr = Bw + blockIdx.x * 128;

    // A: 128 rows x 32 cols = 1024 float4; idx = tid + L*256, L=0..3
    // B: 32 rows x 128 cols = 1024 float4
    int ar  = tid >> 3;              // row for L (L adds 32)
    int akk = (tid & 7) << 2;        // 0,4,...,28
    int bkk = tid >> 5;              // k-row for L (L adds 8)
    int bn4 = (tid & 31) << 2;

    int ntk = K >> 5;                // 32 slabs

    // prologue: stages 0,1
    #pragma unroll
    for (int ps = 0; ps < 2; ps++) {
        int kt = ps << 5;
        unsigned* Asp = As + ps * G2_STAGE_A;
        unsigned* Bsp = Bs + ps * G2_STAGE_B;
        #pragma unroll
        for (int L = 0; L < 4; L++) {
            int r = ar + L * 32;
            cp16(&Asp[r * GA2 + akk], Aptr + (size_t)r * K + kt + akk);
            int kk = bkk + L * 8;
            cp16(&Bsp[kk * GB2 + bn4], Bptr + (size_t)(kt + kk) * N + bn4);
        }
        CP_COMMIT();
    }

    float acc[2][8][4];
    #pragma unroll
    for (int mt = 0; mt < 2; mt++)
        #pragma unroll
        for (int nt = 0; nt < 8; nt++)
            #pragma unroll
            for (int r = 0; r < 4; r++) acc[mt][nt][r] = 0.0f;

    for (int t = 0; t < ntk; t++) {
        if (t + 2 < ntk) {
            int kt = (t + 2) << 5;
            int ns = (t + 2) % 3;
            unsigned* Asp = As + ns * G2_STAGE_A;
            unsigned* Bsp = Bs + ns * G2_STAGE_B;
            #pragma unroll
            for (int L = 0; L < 4; L++) {
                int r = ar + L * 32;
                cp16(&Asp[r * GA2 + akk], Aptr + (size_t)r * K + kt + akk);
                int kk = bkk + L * 8;
                cp16(&Bsp[kk * GB2 + bn4], Bptr + (size_t)(kt + kk) * N + bn4);
            }
        }
        CP_COMMIT();           // commit every iter (possibly empty) -> exact group math
        CP_WAIT(2);            // oldest (stage t) complete
        __syncthreads();

        const unsigned* Asl = As + (t % 3) * G2_STAGE_A;
        const unsigned* Bsl = Bs + (t % 3) * G2_STAGE_B;
        #pragma unroll
        for (int ks = 0; ks < 4; ks++) {
            int k0 = ks * 8;
            unsigned af[2][4];
            #pragma unroll
            for (int mt = 0; mt < 2; mt++) {
                int mb = warp_m * 32 + mt * 16;
                af[mt][0] = Asl[(mb + lg) * GA2 + k0 + lq];
                af[mt][1] = Asl[(mb + 8 + lg) * GA2 + k0 + lq];
                af[mt][2] = Asl[(mb + lg) * GA2 + k0 + 4 + lq];
                af[mt][3] = Asl[(mb + 8 + lg) * GA2 + k0 + 4 + lq];
            }
            #pragma unroll
            for (int nt = 0; nt < 8; nt++) {
                int nb = warp_n * 64 + nt * 8;
                unsigned b0 = Bsl[(k0 + lq) * GB2 + nb + lg];
                unsigned b1 = Bsl[(k0 + 4 + lq) * GB2 + nb + lg];
                #pragma unroll
                for (int mt = 0; mt < 2; mt++)
                    mma_tf32(acc[mt][nt][0], acc[mt][nt][1], acc[mt][nt][2], acc[mt][nt][3],
                             af[mt][0], af[mt][1], af[mt][2], af[mt][3], b0, b1);
            }
        }
        __syncthreads();
    }

    #pragma unroll
    for (int mt = 0; mt < 2; mt++) {
        int row0 = blockIdx.y * 128 + warp_m * 32 + mt * 16 + lg;
        #pragma unroll
        for (int nt = 0; nt < 8; nt++) {
            int col = blockIdx.x * 128 + warp_n * 64 + nt * 8 + 2 * lq;
            float b0 = bias[col], b1 = bias[col + 1];
            float r00 = acc[mt][nt][0] + b0, r01 = acc[mt][nt][1] + b1;
            float r10 = acc[mt][nt][2] + b0, r11 = acc[mt][nt][3] + b1;
            if (round_out) {
                r00 = __uint_as_float(f2tf32(r00));
                r01 = __uint_as_float(f2tf32(r01));
                r10 = __uint_as_float(f2tf32(r10));
                r11 = __uint_as_float(f2tf32(r11));
            }
            *(float2*)(C + (size_t)row0 * N + col) = make_float2(r00, r01);
            *(float2*)(C + (size_t)(row0 + 8) * N + col) = make_float2(r10, r11);
        }
    }
}

// ============================================================
// Kernel 3: flash attention v7 = v6 + single-MUFU ex2.approx.
// block 128 (4 warps), Q tile 128 rows, warp tile 32x64,
// KV 64-key tiles double-buffered, P via register shuffles. 2 CTAs/SM.
// ============================================================
#define AQ_STR 72
#define ATT_SMEM_WORDS (128*AQ_STR + 2*64*AQ_STR + 2*64*AQ_STR)   // 27648 w

__global__ __launch_bounds__(128, 2) void attn_tc7(const float* __restrict__ QKV,
                                                   float* __restrict__ cat)
{
    extern __shared__ unsigned sm[];
    unsigned* Qs = sm;                    // [128][72]  (permuted dk)
    unsigned* Ks = sm + 128 * AQ_STR;     // [2][64][72] (permuted dk)
    unsigned* Vs = Ks + 2 * 64 * AQ_STR;  // [2][64][72] (natural dk)

    int tid  = threadIdx.x;
    int lane = tid & 31;
    int w    = tid >> 5;
    int lg = lane >> 2;
    int lq = lane & 3;
    int rbase = w * 32;

    int bh = blockIdx.y;
    int b = bh >> 4;
    int h = bh & 15;
    int s0 = blockIdx.x * 128;

    const float* Qbase = QKV + (size_t)(b * SS) * N3 + h * DKK;
    const float* Kbase = Qbase + 1024;
    const float* Vbase = Qbase + 2048;

    int kvr  = tid >> 4;
    int kvc4 = (tid & 15) << 2;

    #pragma unroll
    for (int L = 0; L < 8; L++) {
        int r = kvr + L * 8;
        cp16(&Ks[r * AQ_STR + kvc4], Kbase + (size_t)r * N3 + kvc4);
        cp16(&Vs[r * AQ_STR + kvc4], Vbase + (size_t)r * N3 + kvc4);
    }
    CP_COMMIT();

    const float QSC = 0.18033688011112042f;   // (1/8)*log2(e)
    #pragma unroll
    for (int L = 0; L < 16; L++) {
        int idx = tid + L * 128;
        int r  = idx >> 4;
        int c4 = (idx & 15) << 2;
        float4 v = *(const float4*)(Qbase + (size_t)(s0 + r) * N3 + c4);
        uint4 o;
        o.x = f2tf32(v.x * QSC);
        o.y = f2tf32(v.y * QSC);
        o.z = f2tf32(v.z * QSC);
        o.w = f2tf32(v.w * QSC);
        *(uint4*)&Qs[r * AQ_STR + c4] = o;
    }

    float o[2][8][4];
    #pragma unroll
    for (int mt = 0; mt < 2; mt++)
        #pragma unroll
        for (int nt = 0; nt < 8; nt++)
            #pragma unroll
            for (int r = 0; r < 4; r++) o[mt][nt][r] = 0.0f;
    float mrun[2][2] = {{-1e30f, -1e30f}, {-1e30f, -1e30f}};
    float lrun[2][2] = {{0.0f, 0.0f}, {0.0f, 0.0f}};

    int L0 = (lane & ~3) | (lq >> 1);
    int L1 = L0 + 2;
    bool sel = (lq & 1);

    const int NT = SS / 64;
    for (int t = 0; t < NT; t++) {
        int st = t & 1;
        if (t + 1 < NT) {
            int kt = (t + 1) * 64;
            unsigned* Kn = Ks + (st ^ 1) * 64 * AQ_STR;
            unsigned* Vn = Vs + (st ^ 1) * 64 * AQ_STR;
            #pragma unroll
            for (int L = 0; L < 8; L++) {
                int r = kvr + L * 8;
                cp16(&Kn[r * AQ_STR + kvc4], Kbase + (size_t)(kt + r) * N3 + kvc4);
                cp16(&Vn[r * AQ_STR + kvc4], Vbase + (size_t)(kt + r) * N3 + kvc4);
            }
            CP_COMMIT();
            CP_WAIT(1);
        } else {
            CP_WAIT(0);
        }
        __syncthreads();

        const unsigned* K_ = Ks + st * 64 * AQ_STR;
        const unsigned* V_ = Vs + st * 64 * AQ_STR;

        // ---- S = Q*K^T : LDS.64 fragments from permuted layout ----
        float s[2][8][4];
        #pragma unroll
        for (int mt = 0; mt < 2; mt++)
            #pragma unroll
            for (int nt = 0; nt < 8; nt++)
                #pragma unroll
                for (int r = 0; r < 4; r++) s[mt][nt][r] = 0.0f;

        #pragma unroll
        for (int ks = 0; ks < 8; ks++) {
            int k0 = ks * 8 + lq * 2;
            unsigned af[2][4];
            #pragma unroll
            for (int mt = 0; mt < 2; mt++) {
                int mb = rbase + mt * 16;
                uint2 qa = *(const uint2*)&Qs[(mb + lg) * AQ_STR + k0];
                uint2 qb = *(const uint2*)&Qs[(mb + 8 + lg) * AQ_STR + k0];
                af[mt][0] = qa.x; af[mt][1] = qb.x; af[mt][2] = qa.y; af[mt][3] = qb.y;
            }
            #pragma unroll
            for (int nt = 0; nt < 8; nt++) {
                uint2 kb = *(const uint2*)&K_[(nt * 8 + lg) * AQ_STR + k0];
                #pragma unroll
                for (int mt = 0; mt < 2; mt++)
                    mma_tf32(s[mt][nt][0], s[mt][nt][1], s[mt][nt][2], s[mt][nt][3],
                             af[mt][0], af[mt][1], af[mt][2], af[mt][3], kb.x, kb.y);
            }
        }

        // ---- online softmax (base 2, single-MUFU ex2) ----
        #pragma unroll
        for (int mt = 0; mt < 2; mt++) {
            float mloc0 = -1e30f, mloc1 = -1e30f;
            #pragma unroll
            for (int nt = 0; nt < 8; nt++) {
                mloc0 = fmaxf(mloc0, fmaxf(s[mt][nt][0], s[mt][nt][1]));
                mloc1 = fmaxf(mloc1, fmaxf(s[mt][nt][2], s[mt][nt][3]));
            }
            #pragma unroll
            for (int off = 1; off <= 2; off <<= 1) {
                mloc0 = fmaxf(mloc0, __shfl_xor_sync(0xffffffffu, mloc0, off));
                mloc1 = fmaxf(mloc1, __shfl_xor_sync(0xffffffffu, mloc1, off));
            }
            float mnew0 = fmaxf(mrun[mt][0], mloc0);
            float mnew1 = fmaxf(mrun[mt][1], mloc1);
            float alpha0 = ex2(mrun[mt][0] - mnew0);
            float alpha1 = ex2(mrun[mt][1] - mnew1);

            float rs0 = 0.0f, rs1 = 0.0f;
            #pragma unroll
            for (int nt = 0; nt < 8; nt++) {
                float p0 = ex2(s[mt][nt][0] - mnew0);
                float p1 = ex2(s[mt][nt][1] - mnew0);
                float p2 = ex2(s[mt][nt][2] - mnew1);
                float p3 = ex2(s[mt][nt][3] - mnew1);
                rs0 += p0 + p1;
                rs1 += p2 + p3;
                s[mt][nt][0] = __uint_as_float(f2tf32(p0));
                s[mt][nt][1] = __uint_as_float(f2tf32(p1));
                s[mt][nt][2] = __uint_as_float(f2tf32(p2));
                s[mt][nt][3] = __uint_as_float(f2tf32(p3));
            }
            #pragma unroll
            for (int off = 1; off <= 2; off <<= 1) {
                rs0 += __shfl_xor_sync(0xffffffffu, rs0, off);
                rs1 += __shfl_xor_sync(0xffffffffu, rs1, off);
            }
            lrun[mt][0] = lrun[mt][0] * alpha0 + rs0;
            lrun[mt][1] = lrun[mt][1] * alpha1 + rs1;
            mrun[mt][0] = mnew0;
            mrun[mt][1] = mnew1;
            #pragma unroll
            for (int nt = 0; nt < 8; nt++) {
                o[mt][nt][0] *= alpha0; o[mt][nt][1] *= alpha0;
                o[mt][nt][2] *= alpha1; o[mt][nt][3] *= alpha1;
            }
        }

        // ---- O += P*V : P A-fragments via shuffles; V frags shared over mt ----
        #pragma unroll
        for (int ks = 0; ks < 8; ks++) {
            unsigned af[2][4];
            #pragma unroll
            for (int mt = 0; mt < 2; mt++) {
                unsigned p0 = __float_as_uint(s[mt][ks][0]);
                unsigned p1 = __float_as_uint(s[mt][ks][1]);
                unsigned p2 = __float_as_uint(s[mt][ks][2]);
                unsigned p3 = __float_as_uint(s[mt][ks][3]);
                unsigned t00 = __shfl_sync(0xffffffffu, p0, L0);
                unsigned t01 = __shfl_sync(0xffffffffu, p1, L0);
                unsigned t02 = __shfl_sync(0xffffffffu, p2, L0);
                unsigned t03 = __shfl_sync(0xffffffffu, p3, L0);
                unsigned t10 = __shfl_sync(0xffffffffu, p0, L1);
                unsigned t11 = __shfl_sync(0xffffffffu, p1, L1);
                unsigned t12 = __shfl_sync(0xffffffffu, p2, L1);
                unsigned t13 = __shfl_sync(0xffffffffu, p3, L1);
                af[mt][0] = sel ? t01 : t00;
                af[mt][1] = sel ? t03 : t02;
                af[mt][2] = sel ? t11 : t10;
                af[mt][3] = sel ? t13 : t12;
            }
            int k0 = ks * 8;
            #pragma unroll
            for (int nt = 0; nt < 8; nt++) {
                unsigned b0 = V_[(k0 + lq) * AQ_STR + nt * 8 + lg];
                unsigned b1 = V_[(k0 + 4 + lq) * AQ_STR + nt * 8 + lg];
                #pragma unroll
                for (int mt = 0; mt < 2; mt++)
                    mma_tf32(o[mt][nt][0], o[mt][nt][1], o[mt][nt][2], o[mt][nt][3],
                             af[mt][0], af[mt][1], af[mt][2], af[mt][3], b0, b1);
            }
        }
        __syncthreads();
    }

    // epilogue
    #pragma unroll
    for (int mt = 0; mt < 2; mt++) {
        float inv0 = 1.0f / lrun[mt][0];
        float inv1 = 1.0f / lrun[mt][1];
        int row = s0 + rbase + mt * 16 + lg;
        #pragma unroll
        for (int nt = 0; nt < 8; nt++) {
            int col = h * DKK + nt * 8 + 2 * lq;
            float2 v0 = make_float2(__uint_as_float(f2tf32(o[mt][nt][0] * inv0)),
                                    __uint_as_float(f2tf32(o[mt][nt][1] * inv0)));
            float2 v1 = make_float2(__uint_as_float(f2tf32(o[mt][nt][2] * inv1)),
                                    __uint_as_float(f2tf32(o[mt][nt][3] * inv1)));
            *(float2*)(cat + (size_t)(b * SS + row) * DOUTT + col) = v0;
            *(float2*)(cat + (size_t)(b * SS + row + 8) * DOUTT + col) = v1;
        }
    }
}

// ============================================================
// launch
// ============================================================
extern "C" void kernel_launch(void* const* d_in, const int* in_sizes, int n_in,
                              void* d_out, int out_size) {
    const float* x  = (const float*)d_in[0];
    const float* Wq = (const float*)d_in[1];
    const float* bq = (const float*)d_in[2];
    const float* Wk = (const float*)d_in[3];
    const float* bk = (const float*)d_in[4];
    const float* Wv = (const float*)d_in[5];
    const float* bv = (const float*)d_in[6];
    const float* Wo = (const float*)d_in[7];
    const float* bo = (const float*)d_in[8];
    float* out = (float*)d_out;

    float *pWqkv, *pbqkv, *pWo, *pxr, *pQKV, *pcat;
    cudaGetSymbolAddress((void**)&pWqkv, g_Wqkv);
    cudaGetSymbolAddress((void**)&pbqkv, g_bqkv);
    cudaGetSymbolAddress((void**)&pWo,   g_Wo);
    cudaGetSymbolAddress((void**)&pxr,   g_xr);
    cudaGetSymbolAddress((void**)&pQKV,  g_QKV);
    cudaGetSymbolAddress((void**)&pcat,  g_cat);

    {
        int n4 = MM * DD / 4;
        round_x_kernel<<<(n4 + 255) / 256, 256>>>(x);
    }
    {
        int total = 3 * DD * HH * DKK;
        pack_weights_kernel<<<(total + 255) / 256, 256>>>(Wq, bq, Wk, bk, Wv, bv, Wo);
    }
    {
        cudaFuncSetAttribute(gemm_tf32_b32, cudaFuncAttributeMaxDynamicSharedMemorySize,
                             GEMM_SMEM_WORDS * (int)sizeof(unsigned));
        dim3 grid(N3 / 128, MM / 128);
        gemm_tf32_b32<<<grid, 256, GEMM_SMEM_WORDS * sizeof(unsigned)>>>(
            pxr, pWqkv, pbqkv, pQKV, MM, N3, DD, 1);
    }
    {
        cudaFuncSetAttribute(attn_tc7, cudaFuncAttributeMaxDynamicSharedMemorySize,
                             ATT_SMEM_WORDS * (int)sizeof(unsigned));
        dim3 grid(SS / 128, BB * HH);
        attn_tc7<<<grid, 128, ATT_SMEM_WORDS * sizeof(unsigned)>>>(pQKV, pcat);
    }
    {
        dim3 grid(DOUTT / 128, MM / 128);
        gemm_tf32_b32<<<grid, 256, GEMM_SMEM_WORDS * sizeof(unsigned)>>>(
            pcat, pWo, bo, out, MM, DOUTT, DD, 0);
    }
}